// round 5
// baseline (speedup 1.0000x reference)
#include <cuda_runtime.h>
#include <cstddef>

// Problem constants
#define BB 8
#define TT 40
#define HH 32
#define WW 32
#define CC 64
#define CM 32
#define HBLK 8
#define THREADS 128

typedef unsigned long long ull;

// Center-t slab only: 10 h-rows (h0-1 .. h0+8), layout [ci][wslot], pitch 35.
// wslot = w+1, data slots 1..32, zero halos at slots 0 and 33, slot 34 pad.
// Pitch 35 (odd): compute LDS (consecutive w) conflict-free AND fill STS
// (consecutive ci, stride 35) conflict-free (3*ci mod 32 all distinct).
#define PITCH 35
#define CROW (32 * PITCH)              // 1120 floats per h-row
#define SMEM_FLOATS (10 * CROW)        // 11200 floats = 44800 B

// Precombined weights [tap][ci][co], taps: 0:t-1 1:t+1 2:h-1 3:h+1 4:w-1 5:w+1 6:center
// 16B alignment required: read with ld.global.nc.v2.b64 (16B).
__device__ __align__(16) float g_wc[7 * 32 * 32];

__global__ void combine_w(const float* __restrict__ wT,
                          const float* __restrict__ wH,
                          const float* __restrict__ wW) {
    int tap = blockIdx.x;
    int r   = threadIdx.x;
    float v;
    switch (tap) {
        case 0: v = wT[r];            break;
        case 1: v = wT[2048 + r];     break;
        case 2: v = wH[r];            break;
        case 3: v = wH[2048 + r];     break;
        case 4: v = wW[r];            break;
        case 5: v = wW[2048 + r];     break;
        default: v = wT[1024 + r] + wH[1024 + r] + wW[1024 + r]; break;
    }
    g_wc[tap * 1024 + r] = v;
}

// ---- packed f32x2 helpers ----
__device__ __forceinline__ ull dup2(float v) {
    ull r;
    asm("mov.b64 %0, {%1, %1};" : "=l"(r) : "f"(v));
    return r;
}
__device__ __forceinline__ void fma2(ull& d, ull a, ull b) {
    asm("fma.rn.f32x2 %0, %1, %2, %0;" : "+l"(d) : "l"(a), "l"(b));
}
__device__ __forceinline__ void ldg_w4(const float* p, ull& a, ull& b) {
    asm("ld.global.nc.v2.b64 {%0, %1}, [%2];" : "=l"(a), "=l"(b) : "l"(p));
}
__device__ __forceinline__ void unpack2(ull v, float& lo, float& hi) {
    asm("mov.b64 {%0, %1}, %2;" : "=f"(lo), "=f"(hi) : "l"(v));
}

// One tap for the pos-pair: 32 co (16 f32x2 pairs), weights uniform (L1-hit).
__device__ __forceinline__ void tap7(ull aA[16], ull aB[16], const float* wq,
                                     ull xa, ull xb) {
    ull W[16];
    ldg_w4(wq + 0,  W[0],  W[1]);
    ldg_w4(wq + 4,  W[2],  W[3]);
    ldg_w4(wq + 8,  W[4],  W[5]);
    ldg_w4(wq + 12, W[6],  W[7]);
    ldg_w4(wq + 16, W[8],  W[9]);
    ldg_w4(wq + 20, W[10], W[11]);
    ldg_w4(wq + 24, W[12], W[13]);
    ldg_w4(wq + 28, W[14], W[15]);
#pragma unroll
    for (int j = 0; j < 16; ++j) {
        fma2(aA[j], xa, W[j]);
        fma2(aB[j], xb, W[j]);
    }
}

__global__ __launch_bounds__(THREADS, 3)
void mvf3_kernel(const float* __restrict__ x, float* __restrict__ out) {
    extern __shared__ float smem[];

    const int tid = threadIdx.x;
    const int bx  = blockIdx.x;
    const int ht  = bx & 3;
    const int tmp = bx >> 2;
    const int t   = tmp % TT;
    const int b   = tmp / TT;
    const int h0  = ht * HBLK;

    const int ci = tid & 31;
    const int ws = tid >> 5;

    // ---- fill center slab: 10 h-rows ----
#pragma unroll
    for (int r = 0; r < 10; ++r) {
        float* dst = smem + r * CROW;
        int h = h0 - 1 + r;
        if (h < 0 || h >= HH) {
            for (int j = tid; j < CROW; j += THREADS) dst[j] = 0.0f;
        } else {
            if (tid < 64) dst[(tid & 31) * PITCH + (tid >> 5) * 33] = 0.0f;  // W halos
            const float* src = x + ((((size_t)b * TT + t) * HH + h) * (size_t)WW) * CC;
#pragma unroll
            for (int p = 0; p < 8; ++p) {
                int w = ws * 8 + p;                 // warp lanes = ci -> coalesced 128B
                dst[ci * PITCH + w + 1] = src[(size_t)w * CC + ci];
            }
        }
    }

    // ---- skip-channel passthrough ----
    for (int j = tid; j < HBLK * WW * 8; j += THREADS) {
        int f4  = j & 7;
        int pos = j >> 3;
        int row = pos >> 5;
        int w   = pos & 31;
        size_t gi = ((((size_t)b * TT + t) * HH + h0 + row) * WW + w) * CC + CM;
        ((float4*)(out + gi))[f4] = ((const float4*)(x + gi))[f4];
    }

    __syncthreads();

    // ---- compute: warp = 32 w; thread = 2 h-adjacent positions x 32 co ----
    const int wid  = tid >> 5;            // 0..3
    const int lane = tid & 31;            // = w
    const int hA   = h0 + 2 * wid;        // pos A row; pos B = hA+1
    const int rA   = 2 * wid + 1;         // slab row of hA

    const float* pUp = smem + (rA - 1) * CROW + lane + 1;
    const float* pA  = smem + rA * CROW + lane + 1;
    const float* pB  = smem + (rA + 1) * CROW + lane + 1;
    const float* pDn = smem + (rA + 2) * CROW + lane + 1;

    const bool tm_ok = (t > 0);
    const bool tp_ok = (t < TT - 1);
    const size_t baseA = ((((size_t)b * TT + t) * HH + hA) * WW + lane) * CC;
    const ptrdiff_t dT = (ptrdiff_t)HH * WW * CC;
    const float* xTmA = x + baseA + (tm_ok ? -dT : 0);   // clamped: valid addr even at t=0
    const float* xTpA = x + baseA + (tp_ok ?  dT : 0);
    const float* xTmB = xTmA + WW * CC;                  // hA+1
    const float* xTpB = xTpA + WW * CC;

    ull accA[16], accB[16];
#pragma unroll
    for (int j = 0; j < 16; ++j) { accA[j] = 0ull; accB[j] = 0ull; }

    const float4 z4 = make_float4(0.f, 0.f, 0.f, 0.f);

    // NOT fully unrolled: full unroll would be ~150KB of SASS (I$ blowout).
    // Body of 4 channels ~19KB fits I$ L1.5.
#pragma unroll 1
    for (int c0 = 0; c0 < 32; c0 += 4) {
        // t +/- 1 values: coalesced 16B gmem loads (channels contiguous)
        float4 tmA4 = tm_ok ? __ldg((const float4*)xTmA + (c0 >> 2)) : z4;
        float4 tmB4 = tm_ok ? __ldg((const float4*)xTmB + (c0 >> 2)) : z4;
        float4 tpA4 = tp_ok ? __ldg((const float4*)xTpA + (c0 >> 2)) : z4;
        float4 tpB4 = tp_ok ? __ldg((const float4*)xTpB + (c0 >> 2)) : z4;
        float tmA[4] = {tmA4.x, tmA4.y, tmA4.z, tmA4.w};
        float tmB[4] = {tmB4.x, tmB4.y, tmB4.z, tmB4.w};
        float tpA[4] = {tpA4.x, tpA4.y, tpA4.z, tpA4.w};
        float tpB[4] = {tpB4.x, tpB4.y, tpB4.z, tpB4.w};

#pragma unroll
        for (int c8 = 0; c8 < 4; ++c8) {
            const int c   = c0 + c8;
            const int off = c * PITCH;

            // 8 full-width LDS per channel (pos-pair shares h-tap rows)
            float up = pUp[off];
            float am = pA[off - 1], a0 = pA[off], ap = pA[off + 1];
            float bm = pB[off - 1], b0 = pB[off], bp = pB[off + 1];
            float dn = pDn[off];

            ull dA0 = dup2(a0), dB0 = dup2(b0);
            const float* wq = g_wc + c * 32;

            tap7(accA, accB, wq + 0 * 1024, dup2(tmA[c8]), dup2(tmB[c8]));  // t-1
            tap7(accA, accB, wq + 1 * 1024, dup2(tpA[c8]), dup2(tpB[c8]));  // t+1
            tap7(accA, accB, wq + 2 * 1024, dup2(up), dA0);                 // h-1
            tap7(accA, accB, wq + 3 * 1024, dB0, dup2(dn));                 // h+1
            tap7(accA, accB, wq + 4 * 1024, dup2(am), dup2(bm));            // w-1
            tap7(accA, accB, wq + 5 * 1024, dup2(ap), dup2(bp));            // w+1
            tap7(accA, accB, wq + 6 * 1024, dA0, dB0);                      // center
        }
    }

    // ---- ReLU + store: 2 positions x 32 co ----
#pragma unroll
    for (int pos = 0; pos < 2; ++pos) {
        const ull* acc = pos ? accB : accA;
        float v[32];
#pragma unroll
        for (int j = 0; j < 16; ++j) {
            float lo, hi;
            unpack2(acc[j], lo, hi);
            v[2 * j]     = fmaxf(lo, 0.0f);
            v[2 * j + 1] = fmaxf(hi, 0.0f);
        }
        size_t go = ((((size_t)b * TT + t) * HH + hA + pos) * WW + lane) * CC;
        float4* o4 = (float4*)(out + go);
#pragma unroll
        for (int q = 0; q < 8; ++q)
            o4[q] = make_float4(v[4 * q], v[4 * q + 1], v[4 * q + 2], v[4 * q + 3]);
    }
}

extern "C" void kernel_launch(void* const* d_in, const int* in_sizes, int n_in,
                              void* d_out, int out_size) {
    const float* x  = (const float*)d_in[0];
    const float* wT = (const float*)d_in[1];
    const float* wH = (const float*)d_in[2];
    const float* wW = (const float*)d_in[3];
    float* out = (float*)d_out;

    combine_w<<<7, 1024>>>(wT, wH, wW);

    const int smem_bytes = SMEM_FLOATS * (int)sizeof(float);   // 44800 B
    cudaFuncSetAttribute(mvf3_kernel, cudaFuncAttributeMaxDynamicSharedMemorySize, smem_bytes);
    const int grid = BB * TT * (HH / HBLK);   // 1280 blocks
    mvf3_kernel<<<grid, THREADS, smem_bytes>>>(x, out);
}

// round 9
// speedup vs baseline: 1.8430x; 1.8430x over previous
#include <cuda_runtime.h>
#include <cuda_fp16.h>
#include <cstdint>
#include <cstddef>

#define BB 8
#define TT 40
#define HH 32
#define WW 32
#define CC 64
#define THREADS 128

typedef unsigned int u32;

// Slab: 449 slots (14 h-rows x 32 w + 1 zero slot), each slot = 32 ci fp16 = 64B
// data + 16B pad -> stride 80B (20 banks: ldmatrix 8-row phases conflict-free).
// Slab rows: 0..5 = center t (h0-1..h0+4), 6..9 = t-1 (h0..h0+3), 10..13 = t+1.
#define SSTR 80
#define NSLOT 448
#define ZSLOT 448
#define SLAB_BYTES ((NSLOT + 1) * SSTR)      // 35920
#define SM_HI 0
#define SM_LO SLAB_BYTES                      // 35920
#define SM_W  (2 * SLAB_BYTES)                // 71840: weights [tap][part][co] rows x 80B
#define W_ROWS (7 * 2 * 32)                   // 448 rows
#define SM_TOTAL (SM_W + W_ROWS * SSTR)       // 107680 B -> 2 CTAs/SM

// Precombined split weights [tap][co][ci] fp16.
// Taps: 0:t-1 1:t+1 2:h-1 3:center(sum) 4:h+1 5:w-1 6:w+1
__device__ __align__(16) __half g_wh[7 * 1024];
__device__ __align__(16) __half g_wl[7 * 1024];

__global__ void combine_w(const float* __restrict__ wT,
                          const float* __restrict__ wH,
                          const float* __restrict__ wW) {
    int tap = blockIdx.x;
    int r   = threadIdx.x;           // dest index = co*32 + ci
    int co = r >> 5, ci = r & 31;
    int si = ci * 32 + co;           // source layout [ci][co]
    float v;
    switch (tap) {
        case 0: v = wT[si];        break;
        case 1: v = wT[2048 + si]; break;
        case 2: v = wH[si];        break;
        case 3: v = wT[1024 + si] + wH[1024 + si] + wW[1024 + si]; break;
        case 4: v = wH[2048 + si]; break;
        case 5: v = wW[si];        break;
        default: v = wW[2048 + si]; break;
    }
    __half hi = __float2half_rn(v);
    __half lo = __float2half_rn(v - __half2float(hi));
    g_wh[tap * 1024 + r] = hi;
    g_wl[tap * 1024 + r] = lo;
}

__device__ __forceinline__ void ldsm4(u32 addr, u32& r0, u32& r1, u32& r2, u32& r3) {
    asm volatile("ldmatrix.sync.aligned.m8n8.x4.shared.b16 {%0,%1,%2,%3}, [%4];"
                 : "=r"(r0), "=r"(r1), "=r"(r2), "=r"(r3) : "r"(addr));
}
__device__ __forceinline__ void mma16816(float d[4], const u32 a[4], const u32 b[2]) {
    asm volatile(
        "mma.sync.aligned.m16n8k16.row.col.f32.f16.f16.f32 "
        "{%0,%1,%2,%3}, {%4,%5,%6,%7}, {%8,%9}, {%0,%1,%2,%3};"
        : "+f"(d[0]), "+f"(d[1]), "+f"(d[2]), "+f"(d[3])
        : "r"(a[0]), "r"(a[1]), "r"(a[2]), "r"(a[3]), "r"(b[0]), "r"(b[1]));
}

__global__ __launch_bounds__(THREADS, 2)
void mvf_mma(const float* __restrict__ x, float* __restrict__ out) {
    extern __shared__ char smem[];
    const int tid  = threadIdx.x;
    const int lane = tid & 31;
    const int wid  = tid >> 5;

    const int bx  = blockIdx.x;
    const int hc  = bx & 7;
    const int tmp = bx >> 3;
    const int t   = tmp % TT;
    const int b   = tmp / TT;
    const int h0  = hc * 4;

    // ---- fill slab: hi/lo fp16 split, 448 slots x 8 chunks of 4 ci ----
    for (int j = tid; j < NSLOT * 8; j += THREADS) {
        int q = j & 7, slot = j >> 3, r = slot >> 5, w = slot & 31;
        int tp, h;
        if (r < 6)       { tp = t;     h = h0 - 1 + r;  }
        else if (r < 10) { tp = t - 1; h = h0 + r - 6;  }
        else             { tp = t + 1; h = h0 + r - 10; }
        float4 v = make_float4(0.f, 0.f, 0.f, 0.f);
        if ((unsigned)tp < TT && (unsigned)h < HH)
            v = __ldg((const float4*)(x + ((((size_t)b * TT + tp) * HH + h) * WW + w) * CC) + q);
        __half2 h01 = __floats2half2_rn(v.x, v.y);
        __half2 h23 = __floats2half2_rn(v.z, v.w);
        float2 f01 = __half22float2(h01), f23 = __half22float2(h23);
        __half2 l01 = __floats2half2_rn(v.x - f01.x, v.y - f01.y);
        __half2 l23 = __floats2half2_rn(v.z - f23.x, v.w - f23.y);
        union { __half2 h2[2]; uint2 u; } ph, pl;
        ph.h2[0] = h01; ph.h2[1] = h23;
        pl.h2[0] = l01; pl.h2[1] = l23;
        char* base = smem + slot * SSTR + q * 8;
        *(uint2*)(base + SM_HI) = ph.u;
        *(uint2*)(base + SM_LO) = pl.u;
    }
    // zero slot (80B each slab)
    if (tid < 10) {
        ((uint2*)(smem + SM_HI + ZSLOT * SSTR))[tid] = make_uint2(0u, 0u);
        ((uint2*)(smem + SM_LO + ZSLOT * SSTR))[tid] = make_uint2(0u, 0u);
    }

    // ---- weights -> smem: 448 rows ([tap][part][co]) x 64B data ----
    for (int j = tid; j < W_ROWS * 8; j += THREADS) {
        int q = j & 7, row = j >> 3;
        int tap = row >> 6, rem = row & 63, part = rem >> 5, co = rem & 31;
        const __half* gsrc = (part ? g_wl : g_wh) + tap * 1024 + co * 32 + q * 4;
        *(uint2*)(smem + SM_W + row * SSTR + q * 8) = *(const uint2*)gsrc;
    }

    // ---- skip-channel passthrough ----
    {
        int r = tid >> 5, w = tid & 31;
        size_t gi = ((((size_t)b * TT + t) * HH + h0 + r) * WW + w) * CC + 32;
        const float4* s4 = (const float4*)(x + gi);
        float4* d4 = (float4*)(out + gi);
#pragma unroll
        for (int q = 0; q < 8; ++q) d4[q] = s4[q];
    }

    __syncthreads();

    // ---- compute: warp = h-row (h0+wid) x 32 w x 32 co ----
    const u32 sbase = (u32)__cvta_generic_to_shared(smem);

    // ldmatrix lane roles: A x4 = (m0-7,k0-7),(m8-15,k0-7),(m0-7,k8-15),(m8-15,k8-15)
    const int amat   = lane >> 3, ar = lane & 7;
    const int a_mloc = (amat & 1) * 8 + ar;       // m row within m16
    const int a_kb   = (amat >> 1) * 16;          // k byte offset (8 fp16 = 16B)
    // B x4 = (nb0,k0-7),(nb0,k8-15),(nb1,k0-7),(nb1,k8-15); rows = co
    const int b_nbh = lane >> 4, b_kh = (lane >> 3) & 1, b_cor = lane & 7;

    int sb[7], dw[7];
    sb[0] = 6 + wid;  dw[0] = 0;    // t-1
    sb[1] = 10 + wid; dw[1] = 0;    // t+1
    sb[2] = wid;      dw[2] = 0;    // h-1
    sb[3] = wid + 1;  dw[3] = 0;    // center
    sb[4] = wid + 2;  dw[4] = 0;    // h+1
    sb[5] = wid + 1;  dw[5] = -1;   // w-1
    sb[6] = wid + 1;  dw[6] = 1;    // w+1

    float D[2][4][4];
#pragma unroll
    for (int mt = 0; mt < 2; ++mt)
#pragma unroll
        for (int nb = 0; nb < 4; ++nb)
#pragma unroll
            for (int k = 0; k < 4; ++k) D[mt][nb][k] = 0.f;

#pragma unroll
    for (int tap = 0; tap < 7; ++tap) {
        // B fragments for this tap: [ks][nb][2], hi and lo
        u32 Bh[2][4][2], Bl[2][4][2];
#pragma unroll
        for (int ks = 0; ks < 2; ++ks) {
#pragma unroll
            for (int pb = 0; pb < 2; ++pb) {
                int co_r = (pb * 2 + b_nbh) * 8 + b_cor;
                u32 off = (u32)(ks * 32 + b_kh * 16);
                u32 ah = sbase + SM_W + (u32)(((tap * 2 + 0) * 32 + co_r) * SSTR) + off;
                u32 al = sbase + SM_W + (u32)(((tap * 2 + 1) * 32 + co_r) * SSTR) + off;
                ldsm4(ah, Bh[ks][pb * 2][0], Bh[ks][pb * 2][1],
                          Bh[ks][pb * 2 + 1][0], Bh[ks][pb * 2 + 1][1]);
                ldsm4(al, Bl[ks][pb * 2][0], Bl[ks][pb * 2][1],
                          Bl[ks][pb * 2 + 1][0], Bl[ks][pb * 2 + 1][1]);
            }
        }
#pragma unroll
        for (int mt = 0; mt < 2; ++mt) {
            int wsrc = mt * 16 + a_mloc + dw[tap];
            int slot = ((unsigned)wsrc < WW) ? sb[tap] * 32 + wsrc : ZSLOT;
            u32 abase = (u32)(slot * SSTR + a_kb);
#pragma unroll
            for (int ks = 0; ks < 2; ++ks) {
                u32 Ah[4], Al[4];
                ldsm4(sbase + SM_HI + abase + ks * 32, Ah[0], Ah[1], Ah[2], Ah[3]);
                ldsm4(sbase + SM_LO + abase + ks * 32, Al[0], Al[1], Al[2], Al[3]);
#pragma unroll
                for (int nb = 0; nb < 4; ++nb) {
                    mma16816(D[mt][nb], Ah, Bh[ks][nb]);
                    mma16816(D[mt][nb], Al, Bh[ks][nb]);
                    mma16816(D[mt][nb], Ah, Bl[ks][nb]);
                }
            }
        }
    }

    // ---- epilogue: ReLU + store (c0,c1 at row grp; c2,c3 at row grp+8) ----
    const int grp = lane >> 2, qd = lane & 3;
    const size_t rowbase = (((size_t)b * TT + t) * HH + h0 + wid) * WW;
#pragma unroll
    for (int mt = 0; mt < 2; ++mt)
#pragma unroll
        for (int nb = 0; nb < 4; ++nb)
#pragma unroll
            for (int hr = 0; hr < 2; ++hr) {
                int wpos = mt * 16 + hr * 8 + grp;
                int co = nb * 8 + qd * 2;
                float2 v;
                v.x = fmaxf(D[mt][nb][hr * 2 + 0], 0.f);
                v.y = fmaxf(D[mt][nb][hr * 2 + 1], 0.f);
                *(float2*)(out + (rowbase + wpos) * CC + co) = v;
            }
}

extern "C" void kernel_launch(void* const* d_in, const int* in_sizes, int n_in,
                              void* d_out, int out_size) {
    const float* x  = (const float*)d_in[0];
    const float* wT = (const float*)d_in[1];
    const float* wH = (const float*)d_in[2];
    const float* wW = (const float*)d_in[3];
    float* out = (float*)d_out;

    combine_w<<<7, 1024>>>(wT, wH, wW);

    cudaFuncSetAttribute(mvf_mma, cudaFuncAttributeMaxDynamicSharedMemorySize, SM_TOTAL);
    mvf_mma<<<BB * TT * 8, THREADS, SM_TOTAL>>>(x, out);
}

// round 11
// speedup vs baseline: 2.2455x; 1.2184x over previous
#include <cuda_runtime.h>
#include <cuda_fp16.h>
#include <cstdint>
#include <cstddef>

#define BB 8
#define TT 40
#define HH 32
#define WW 32
#define CC 64
#define THREADS 128

typedef unsigned int u32;

// Slab: 449 slots (14 h-rows x 32 w + 1 zero slot), each slot = 32 ci fp16 = 64B
// data + 16B pad -> stride 80B (16B-aligned for ldmatrix; 8-row phases conflict-free).
// Slab rows: 0..5 = center t (h0-1..h0+4), 6..9 = t-1 (h0..h0+3), 10..13 = t+1.
#define SSTR 80
#define NSLOT 448
#define ZSLOT 448
#define SLAB_BYTES ((NSLOT + 1) * SSTR)      // 35920
#define SM_HI 0
#define SM_LO SLAB_BYTES                      // 35920
#define SM_TOTAL (2 * SLAB_BYTES)             // 71840 B -> 3 CTAs/SM

// B fragments precomputed in ldmatrix-output order:
// g_btbl[tap][part][ks][pb][lane] = uint4( B[pb*2][0], B[pb*2][1], B[pb*2+1][0], B[pb*2+1][1] )
// where component c encodes matrix i=c: co=(pb*2+(i>>1))*8+(lane>>2),
// ci pair = ks*16+(i&1)*8+2*(lane&3) (+0,+1), packed fp16x2 (low half = first ci).
// Taps: 0:t-1 1:t+1 2:h-1 3:center(sum) 4:h+1 5:w-1 6:w+1
__device__ __align__(16) uint4 g_btbl[7 * 2 * 2 * 2 * 32];   // 28672 B

__device__ __forceinline__ float getw(int tap, int co, int ci,
                                      const float* wT, const float* wH, const float* wW) {
    int si = ci * 32 + co;            // source [kt][ci][co]
    switch (tap) {
        case 0: return wT[si];
        case 1: return wT[2048 + si];
        case 2: return wH[si];
        case 3: return wT[1024 + si] + wH[1024 + si] + wW[1024 + si];
        case 4: return wH[2048 + si];
        case 5: return wW[si];
        default: return wW[2048 + si];
    }
}

__global__ void prep_w(const float* __restrict__ wT,
                       const float* __restrict__ wH,
                       const float* __restrict__ wW) {
    int tap  = blockIdx.x;                       // 7 blocks x 256 threads
    int tx   = threadIdx.x;
    int part = tx >> 7;
    int ks   = (tx >> 6) & 1;
    int pb   = (tx >> 5) & 1;
    int lane = tx & 31;

    u32 comp[4];
#pragma unroll
    for (int c = 0; c < 4; ++c) {                // c = matrix index i
        int co  = (pb * 2 + (c >> 1)) * 8 + (lane >> 2);
        int ci0 = ks * 16 + (c & 1) * 8 + 2 * (lane & 3);
        __half p[2];
#pragma unroll
        for (int e = 0; e < 2; ++e) {
            float v  = getw(tap, co, ci0 + e, wT, wH, wW);
            __half h = __float2half_rn(v);
            p[e] = part ? __float2half_rn(v - __half2float(h)) : h;
        }
        comp[c] = ((u32)__half_as_ushort(p[1]) << 16) | (u32)__half_as_ushort(p[0]);
    }
    int idx = (((tap * 2 + part) * 2 + ks) * 2 + pb) * 32 + lane;
    g_btbl[idx] = make_uint4(comp[0], comp[1], comp[2], comp[3]);
}

__device__ __forceinline__ void ldsm4(u32 addr, u32& r0, u32& r1, u32& r2, u32& r3) {
    asm volatile("ldmatrix.sync.aligned.m8n8.x4.shared.b16 {%0,%1,%2,%3}, [%4];"
                 : "=r"(r0), "=r"(r1), "=r"(r2), "=r"(r3) : "r"(addr));
}
__device__ __forceinline__ void mma16816(float d[4], const u32 a[4], const u32 b[2]) {
    asm volatile(
        "mma.sync.aligned.m16n8k16.row.col.f32.f16.f16.f32 "
        "{%0,%1,%2,%3}, {%4,%5,%6,%7}, {%8,%9}, {%0,%1,%2,%3};"
        : "+f"(d[0]), "+f"(d[1]), "+f"(d[2]), "+f"(d[3])
        : "r"(a[0]), "r"(a[1]), "r"(a[2]), "r"(a[3]), "r"(b[0]), "r"(b[1]));
}

__global__ __launch_bounds__(THREADS, 3)
void mvf_mma(const float* __restrict__ x, float* __restrict__ out) {
    extern __shared__ char smem[];
    const int tid  = threadIdx.x;
    const int lane = tid & 31;
    const int wid  = tid >> 5;

    const int bx  = blockIdx.x;
    const int hc  = bx & 7;
    const int tmp = bx >> 3;
    const int t   = tmp % TT;
    const int b   = tmp / TT;
    const int h0  = hc * 4;

    // ---- fill slab: hi/lo fp16 split, 448 slots x 8 chunks of 4 ci ----
    for (int j = tid; j < NSLOT * 8; j += THREADS) {
        int q = j & 7, slot = j >> 3, r = slot >> 5, w = slot & 31;
        int tp, h;
        if (r < 6)       { tp = t;     h = h0 - 1 + r;  }
        else if (r < 10) { tp = t - 1; h = h0 + r - 6;  }
        else             { tp = t + 1; h = h0 + r - 10; }
        float4 v = make_float4(0.f, 0.f, 0.f, 0.f);
        if ((unsigned)tp < TT && (unsigned)h < HH)
            v = __ldg((const float4*)(x + ((((size_t)b * TT + tp) * HH + h) * WW + w) * CC) + q);
        __half2 h01 = __floats2half2_rn(v.x, v.y);
        __half2 h23 = __floats2half2_rn(v.z, v.w);
        float2 f01 = __half22float2(h01), f23 = __half22float2(h23);
        __half2 l01 = __floats2half2_rn(v.x - f01.x, v.y - f01.y);
        __half2 l23 = __floats2half2_rn(v.z - f23.x, v.w - f23.y);
        union { __half2 h2[2]; uint2 u; } ph, pl;
        ph.h2[0] = h01; ph.h2[1] = h23;
        pl.h2[0] = l01; pl.h2[1] = l23;
        char* base = smem + slot * SSTR + q * 8;
        *(uint2*)(base + SM_HI) = ph.u;
        *(uint2*)(base + SM_LO) = pl.u;
    }
    // zero slot (80B each slab)
    if (tid < 10) {
        ((uint2*)(smem + SM_HI + ZSLOT * SSTR))[tid] = make_uint2(0u, 0u);
        ((uint2*)(smem + SM_LO + ZSLOT * SSTR))[tid] = make_uint2(0u, 0u);
    }

    // ---- skip-channel passthrough ----
    {
        int r = tid >> 5, w = tid & 31;
        size_t gi = ((((size_t)b * TT + t) * HH + h0 + r) * WW + w) * CC + 32;
        const float4* s4 = (const float4*)(x + gi);
        float4* d4 = (float4*)(out + gi);
#pragma unroll
        for (int q = 0; q < 8; ++q) d4[q] = s4[q];
    }

    __syncthreads();

    // ---- compute: warp = h-row (h0+wid) x 32 w x 32 co ----
    const u32 sbase = (u32)__cvta_generic_to_shared(smem);

    // A ldmatrix lane roles: x4 = (m0-7,k0-7),(m8-15,k0-7),(m0-7,k8-15),(m8-15,k8-15)
    const int amat   = lane >> 3, ar = lane & 7;
    const int a_mloc = (amat & 1) * 8 + ar;       // m row within m16
    const int a_kb   = (amat >> 1) * 16;          // k byte offset

    int sb[7], dw[7];
    sb[0] = 6 + wid;  dw[0] = 0;    // t-1
    sb[1] = 10 + wid; dw[1] = 0;    // t+1
    sb[2] = wid;      dw[2] = 0;    // h-1
    sb[3] = wid + 1;  dw[3] = 0;    // center
    sb[4] = wid + 2;  dw[4] = 0;    // h+1
    sb[5] = wid + 1;  dw[5] = -1;   // w-1
    sb[6] = wid + 1;  dw[6] = 1;    // w+1

    float D[2][4][4];
#pragma unroll
    for (int mt = 0; mt < 2; ++mt)
#pragma unroll
        for (int nb = 0; nb < 4; ++nb)
#pragma unroll
            for (int k = 0; k < 4; ++k) D[mt][nb][k] = 0.f;

#pragma unroll
    for (int tap = 0; tap < 7; ++tap) {
        // B fragments: 8 x LDG.128 from the precomputed L1-resident table
        u32 Bh[2][4][2], Bl[2][4][2];
#pragma unroll
        for (int part = 0; part < 2; ++part)
#pragma unroll
            for (int ks = 0; ks < 2; ++ks)
#pragma unroll
                for (int pb = 0; pb < 2; ++pb) {
                    uint4 v = __ldg(&g_btbl[(((tap * 2 + part) * 2 + ks) * 2 + pb) * 32 + lane]);
                    u32 (*B)[4][2] = part ? Bl : Bh;
                    B[ks][pb * 2][0]     = v.x; B[ks][pb * 2][1]     = v.y;
                    B[ks][pb * 2 + 1][0] = v.z; B[ks][pb * 2 + 1][1] = v.w;
                }
#pragma unroll
        for (int mt = 0; mt < 2; ++mt) {
            int wsrc = mt * 16 + a_mloc + dw[tap];
            int slot = ((unsigned)wsrc < WW) ? sb[tap] * 32 + wsrc : ZSLOT;
            u32 abase = (u32)(slot * SSTR + a_kb);
#pragma unroll
            for (int ks = 0; ks < 2; ++ks) {
                u32 Ah[4], Al[4];
                ldsm4(sbase + SM_HI + abase + ks * 32, Ah[0], Ah[1], Ah[2], Ah[3]);
                ldsm4(sbase + SM_LO + abase + ks * 32, Al[0], Al[1], Al[2], Al[3]);
#pragma unroll
                for (int nb = 0; nb < 4; ++nb) {
                    mma16816(D[mt][nb], Ah, Bh[ks][nb]);
                    mma16816(D[mt][nb], Al, Bh[ks][nb]);
                    mma16816(D[mt][nb], Ah, Bl[ks][nb]);
                }
            }
        }
    }

    // ---- epilogue: ReLU + store (c0,c1 at row grp; c2,c3 at row grp+8) ----
    const int grp = lane >> 2, qd = lane & 3;
    const size_t rowbase = (((size_t)b * TT + t) * HH + h0 + wid) * WW;
#pragma unroll
    for (int mt = 0; mt < 2; ++mt)
#pragma unroll
        for (int nb = 0; nb < 4; ++nb)
#pragma unroll
            for (int hr = 0; hr < 2; ++hr) {
                int wpos = mt * 16 + hr * 8 + grp;
                int co = nb * 8 + qd * 2;
                float2 v;
                v.x = fmaxf(D[mt][nb][hr * 2 + 0], 0.f);
                v.y = fmaxf(D[mt][nb][hr * 2 + 1], 0.f);
                *(float2*)(out + (rowbase + wpos) * CC + co) = v;
            }
}

extern "C" void kernel_launch(void* const* d_in, const int* in_sizes, int n_in,
                              void* d_out, int out_size) {
    const float* x  = (const float*)d_in[0];
    const float* wT = (const float*)d_in[1];
    const float* wH = (const float*)d_in[2];
    const float* wW = (const float*)d_in[3];
    float* out = (float*)d_out;

    prep_w<<<7, 256>>>(wT, wH, wW);

    cudaFuncSetAttribute(mvf_mma, cudaFuncAttributeMaxDynamicSharedMemorySize, SM_TOTAL);
    mvf_mma<<<BB * TT * 8, THREADS, SM_TOTAL>>>(x, out);
}

// round 12
// speedup vs baseline: 2.8213x; 1.2564x over previous
#include <cuda_runtime.h>
#include <cuda_fp16.h>
#include <cstdint>
#include <cstddef>

#define BB 8
#define TT 40
#define HH 32
#define WW 32
#define CC 64
#define THREADS 128

typedef unsigned int u32;

// Slab (single, fp16): 449 slots (14 h-rows x 32 w + 1 zero slot), 32 ci fp16 = 64B
// data + 16B pad -> stride 80B (16B-aligned ldmatrix rows; 8-row phases conflict-free).
// Slab rows: 0..5 = center t (h0-1..h0+4), 6..9 = t-1 (h0..h0+3), 10..13 = t+1.
#define SSTR 80
#define NSLOT 448
#define ZSLOT 448
#define SM_TOTAL ((NSLOT + 1) * SSTR)        // 35920 B -> 4 CTAs/SM (reg-capped)

// B fragments precomputed in ldmatrix-output order (hi limb + lo residual of weights):
// g_btbl[tap][part][ks][pb][lane] = uint4 of matrices i=0..3:
//   co=(pb*2+(i>>1))*8+(lane>>2), ci pair = ks*16+(i&1)*8+2*(lane&3) (+0,+1),
//   packed fp16x2 low-half-first.
// Taps: 0:t-1 1:t+1 2:h-1 3:center(sum) 4:h+1 5:w-1 6:w+1
__device__ __align__(16) uint4 g_btbl[7 * 2 * 2 * 2 * 32];   // 28672 B

__device__ __forceinline__ float getw(int tap, int co, int ci,
                                      const float* wT, const float* wH, const float* wW) {
    int si = ci * 32 + co;            // source [kt][ci][co]
    switch (tap) {
        case 0: return wT[si];
        case 1: return wT[2048 + si];
        case 2: return wH[si];
        case 3: return wT[1024 + si] + wH[1024 + si] + wW[1024 + si];
        case 4: return wH[2048 + si];
        case 5: return wW[si];
        default: return wW[2048 + si];
    }
}

__global__ void prep_w(const float* __restrict__ wT,
                       const float* __restrict__ wH,
                       const float* __restrict__ wW) {
    int tap  = blockIdx.x;                       // 7 blocks x 256 threads
    int tx   = threadIdx.x;
    int part = tx >> 7;
    int ks   = (tx >> 6) & 1;
    int pb   = (tx >> 5) & 1;
    int lane = tx & 31;

    u32 comp[4];
#pragma unroll
    for (int c = 0; c < 4; ++c) {                // c = matrix index i
        int co  = (pb * 2 + (c >> 1)) * 8 + (lane >> 2);
        int ci0 = ks * 16 + (c & 1) * 8 + 2 * (lane & 3);
        __half p[2];
#pragma unroll
        for (int e = 0; e < 2; ++e) {
            float v  = getw(tap, co, ci0 + e, wT, wH, wW);
            __half h = __float2half_rn(v);
            p[e] = part ? __float2half_rn(v - __half2float(h)) : h;
        }
        comp[c] = ((u32)__half_as_ushort(p[1]) << 16) | (u32)__half_as_ushort(p[0]);
    }
    int idx = (((tap * 2 + part) * 2 + ks) * 2 + pb) * 32 + lane;
    g_btbl[idx] = make_uint4(comp[0], comp[1], comp[2], comp[3]);
}

__device__ __forceinline__ void ldsm4(u32 addr, u32& r0, u32& r1, u32& r2, u32& r3) {
    asm volatile("ldmatrix.sync.aligned.m8n8.x4.shared.b16 {%0,%1,%2,%3}, [%4];"
                 : "=r"(r0), "=r"(r1), "=r"(r2), "=r"(r3) : "r"(addr));
}
__device__ __forceinline__ void mma16816(float d[4], const u32 a[4], const u32 b[2]) {
    asm volatile(
        "mma.sync.aligned.m16n8k16.row.col.f32.f16.f16.f32 "
        "{%0,%1,%2,%3}, {%4,%5,%6,%7}, {%8,%9}, {%0,%1,%2,%3};"
        : "+f"(d[0]), "+f"(d[1]), "+f"(d[2]), "+f"(d[3])
        : "r"(a[0]), "r"(a[1]), "r"(a[2]), "r"(a[3]), "r"(b[0]), "r"(b[1]));
}

__global__ __launch_bounds__(THREADS, 4)
void mvf_mma(const float* __restrict__ x, float* __restrict__ out) {
    extern __shared__ char smem[];
    const int tid  = threadIdx.x;
    const int lane = tid & 31;
    const int wid  = tid >> 5;

    const int bx  = blockIdx.x;
    const int hc  = bx & 7;
    const int tmp = bx >> 3;
    const int t   = tmp % TT;
    const int b   = tmp / TT;
    const int h0  = hc * 4;

    // ---- fill slab: x rounded to fp16 (A-lo limb dropped; B keeps hi+lo) ----
    for (int j = tid; j < NSLOT * 8; j += THREADS) {
        int q = j & 7, slot = j >> 3, r = slot >> 5, w = slot & 31;
        int tp, h;
        if (r < 6)       { tp = t;     h = h0 - 1 + r;  }
        else if (r < 10) { tp = t - 1; h = h0 + r - 6;  }
        else             { tp = t + 1; h = h0 + r - 10; }
        float4 v = make_float4(0.f, 0.f, 0.f, 0.f);
        if ((unsigned)tp < TT && (unsigned)h < HH)
            v = __ldg((const float4*)(x + ((((size_t)b * TT + tp) * HH + h) * WW + w) * CC) + q);
        union { __half2 h2[2]; uint2 u; } ph;
        ph.h2[0] = __floats2half2_rn(v.x, v.y);
        ph.h2[1] = __floats2half2_rn(v.z, v.w);
        *(uint2*)(smem + slot * SSTR + q * 8) = ph.u;
    }
    // zero slot (80B)
    if (tid < 10)
        ((uint2*)(smem + ZSLOT * SSTR))[tid] = make_uint2(0u, 0u);

    // ---- skip-channel passthrough ----
    {
        int r = tid >> 5, w = tid & 31;
        size_t gi = ((((size_t)b * TT + t) * HH + h0 + r) * WW + w) * CC + 32;
        const float4* s4 = (const float4*)(x + gi);
        float4* d4 = (float4*)(out + gi);
#pragma unroll
        for (int q = 0; q < 8; ++q) d4[q] = s4[q];
    }

    __syncthreads();

    // ---- compute: warp = h-row (h0+wid) x 32 w x 32 co ----
    const u32 sbase = (u32)__cvta_generic_to_shared(smem);

    // A ldmatrix lane roles: x4 = (m0-7,k0-7),(m8-15,k0-7),(m0-7,k8-15),(m8-15,k8-15)
    const int amat   = lane >> 3, ar = lane & 7;
    const int a_mloc = (amat & 1) * 8 + ar;       // m row within m16
    const int a_kb   = (amat >> 1) * 16;          // k byte offset

    int sb[7], dw[7];
    sb[0] = 6 + wid;  dw[0] = 0;    // t-1
    sb[1] = 10 + wid; dw[1] = 0;    // t+1
    sb[2] = wid;      dw[2] = 0;    // h-1
    sb[3] = wid + 1;  dw[3] = 0;    // center
    sb[4] = wid + 2;  dw[4] = 0;    // h+1
    sb[5] = wid + 1;  dw[5] = -1;   // w-1
    sb[6] = wid + 1;  dw[6] = 1;    // w+1

    float D[2][4][4];
#pragma unroll
    for (int mt = 0; mt < 2; ++mt)
#pragma unroll
        for (int nb = 0; nb < 4; ++nb)
#pragma unroll
            for (int k = 0; k < 4; ++k) D[mt][nb][k] = 0.f;

#pragma unroll
    for (int tap = 0; tap < 7; ++tap) {
        // B fragments: 8 x LDG.128 from the precomputed L1-resident table
        u32 Bh[2][4][2], Bl[2][4][2];
#pragma unroll
        for (int part = 0; part < 2; ++part)
#pragma unroll
            for (int ks = 0; ks < 2; ++ks)
#pragma unroll
                for (int pb = 0; pb < 2; ++pb) {
                    uint4 v = __ldg(&g_btbl[(((tap * 2 + part) * 2 + ks) * 2 + pb) * 32 + lane]);
                    u32 (*B)[4][2] = part ? Bl : Bh;
                    B[ks][pb * 2][0]     = v.x; B[ks][pb * 2][1]     = v.y;
                    B[ks][pb * 2 + 1][0] = v.z; B[ks][pb * 2 + 1][1] = v.w;
                }
#pragma unroll
        for (int mt = 0; mt < 2; ++mt) {
            int wsrc = mt * 16 + a_mloc + dw[tap];
            int slot = ((unsigned)wsrc < WW) ? sb[tap] * 32 + wsrc : ZSLOT;
            u32 abase = (u32)(slot * SSTR + a_kb);
#pragma unroll
            for (int ks = 0; ks < 2; ++ks) {
                u32 Ah[4];
                ldsm4(sbase + abase + ks * 32, Ah[0], Ah[1], Ah[2], Ah[3]);
#pragma unroll
                for (int nb = 0; nb < 4; ++nb) {
                    mma16816(D[mt][nb], Ah, Bh[ks][nb]);
                    mma16816(D[mt][nb], Ah, Bl[ks][nb]);
                }
            }
        }
    }

    // ---- epilogue: ReLU + store (c0,c1 at row grp; c2,c3 at row grp+8) ----
    const int grp = lane >> 2, qd = lane & 3;
    const size_t rowbase = (((size_t)b * TT + t) * HH + h0 + wid) * WW;
#pragma unroll
    for (int mt = 0; mt < 2; ++mt)
#pragma unroll
        for (int nb = 0; nb < 4; ++nb)
#pragma unroll
            for (int hr = 0; hr < 2; ++hr) {
                int wpos = mt * 16 + hr * 8 + grp;
                int co = nb * 8 + qd * 2;
                float2 v;
                v.x = fmaxf(D[mt][nb][hr * 2 + 0], 0.f);
                v.y = fmaxf(D[mt][nb][hr * 2 + 1], 0.f);
                *(float2*)(out + (rowbase + wpos) * CC + co) = v;
            }
}

extern "C" void kernel_launch(void* const* d_in, const int* in_sizes, int n_in,
                              void* d_out, int out_size) {
    const float* x  = (const float*)d_in[0];
    const float* wT = (const float*)d_in[1];
    const float* wH = (const float*)d_in[2];
    const float* wW = (const float*)d_in[3];
    float* out = (float*)d_out;

    prep_w<<<7, 256>>>(wT, wH, wW);

    cudaFuncSetAttribute(mvf_mma, cudaFuncAttributeMaxDynamicSharedMemorySize, SM_TOTAL);
    mvf_mma<<<BB * TT * 8, THREADS, SM_TOTAL>>>(x, out);
}